// round 7
// baseline (speedup 1.0000x reference)
#include <cuda_runtime.h>
#include <cuda_fp16.h>
#include <math.h>

#define WARPS_PER_BLOCK 8
#define THREADS_PER_BLOCK (WARPS_PER_BLOCK * 32)
#define FULL_MASK 0xffffffffu
#define MAX_NODES 100000
#define FEAT 64

// fp16 staging of node_value: one row = 64 halves = 128B = ONE L2 line.
// Viewed as uint2: 16 uint2 per row; lane sub owns features [4*sub, 4*sub+4).
__device__ uint2 g_value_h[(size_t)MAX_NODES * (FEAT / 4)];

// Index width (int32 vs int64) detected from raw words of row_ptr:
//   int32: [0, D, 2D, ...]  -> raw[1] != 0
//   int64: [0,0, D,0, ...]  -> raw[1] == 0 && raw[2] != 0
__device__ __forceinline__ long long load_index(const void* p, long long i, int is64)
{
    return is64 ? ((const long long*)p)[i] : (long long)((const int*)p)[i];
}

__global__ void __launch_bounds__(256)
convert_to_half_kernel(const float4* __restrict__ node_value4, int n_f4)
{
    const int i = blockIdx.x * blockDim.x + threadIdx.x;
    if (i < n_f4) {
        const float4 f = node_value4[i];
        uint2 h;
        *reinterpret_cast<__half2*>(&h.x) = __floats2half2_rn(f.x, f.y);
        *reinterpret_cast<__half2*>(&h.y) = __floats2half2_rn(f.z, f.w);
        g_value_h[i] = h;
    }
}

// TWO nodes per warp (their 32 CSR edges are contiguous). All 32 lanes load
// one score+col; butterfly offsets 8,4,2,1 give an independent softmax per
// 16-lane half (one node each). Gather: lane owns 4 features as one uint2
// (fp16x4); a single warp-wide LDG.64 serves one edge of EACH node = 2 lines.
__global__ void __launch_bounds__(THREADS_PER_BLOCK)
gat_aggregate_kernel(const void*   __restrict__ row_ptr_raw,
                     const void*   __restrict__ col_idx_raw,
                     const float*  __restrict__ edge_scores,
                     const float4* __restrict__ node_value4,  // fp32 fallback
                     float4*       __restrict__ out4,         // [N, 16] float4
                     int num_nodes)
{
    const int pair = blockIdx.x * WARPS_PER_BLOCK + (threadIdx.x >> 5);
    const int nodeA = 2 * pair;
    if (nodeA >= num_nodes) return;
    const int lane = threadIdx.x & 31;
    const int half = lane >> 4;
    const int sub  = lane & 15;

    // uniform per-grid: detect index width (L2-broadcast loads, ~free)
    const unsigned* rp_raw = (const unsigned*)row_ptr_raw;
    const int is64 = (rp_raw[1] == 0u && rp_raw[2] != 0u) ? 1 : 0;

    const long long start = load_index(row_ptr_raw, nodeA, is64);
    const bool haveB = (nodeA + 1) < num_nodes;
    const long long mid = haveB ? load_index(row_ptr_raw, nodeA + 1, is64) : start;
    const long long end = haveB ? load_index(row_ptr_raw, nodeA + 2, is64) : mid;

    if (haveB && (mid - start) == 16 && (end - mid) == 16 &&
        num_nodes <= MAX_NODES) {
        // ---- fast path: both nodes degree 16, fp16-staged gather ----
        const float    s = edge_scores[start + lane];
        const unsigned c = (unsigned)load_index(col_idx_raw, start + lane, is64);

        // per-half softmax (halves never mix with offsets <= 8)
        float m = s;
        #pragma unroll
        for (int off = 8; off > 0; off >>= 1)
            m = fmaxf(m, __shfl_xor_sync(FULL_MASK, m, off));

        float w = __expf(s - m);
        float sum = w;
        #pragma unroll
        for (int off = 8; off > 0; off >>= 1)
            sum += __shfl_xor_sync(FULL_MASK, sum, off);

        w *= __frcp_rn(sum);

        const int base = half << 4;   // this half reads its own node's edges
        float4 acc = make_float4(0.0f, 0.0f, 0.0f, 0.0f);
        #pragma unroll
        for (int e = 0; e < 16; e++) {
            const float    bw = __shfl_sync(FULL_MASK, w, base + e);
            const unsigned bc = __shfl_sync(FULL_MASK, c, base + e);
            const uint2 hv = g_value_h[(size_t)bc * 16 + sub];
            const float2 v01 = __half22float2(*reinterpret_cast<const __half2*>(&hv.x));
            const float2 v23 = __half22float2(*reinterpret_cast<const __half2*>(&hv.y));
            acc.x = fmaf(bw, v01.x, acc.x);
            acc.y = fmaf(bw, v01.y, acc.y);
            acc.z = fmaf(bw, v23.x, acc.z);
            acc.w = fmaf(bw, v23.y, acc.w);
        }

        out4[(size_t)(nodeA + half) * 16 + sub] = acc;
    } else {
        // ---- generic path: any degree, full fp32 (not taken here) ----
        for (int which = 0; which < 2; which++) {
            const int node = nodeA + which;
            if (node >= num_nodes) break;
            const long long s0 = load_index(row_ptr_raw, node, is64);
            const long long s1 = load_index(row_ptr_raw, node + 1, is64);
            const int deg = (int)(s1 - s0);

            float m = -INFINITY;
            for (int e = lane; e < deg; e += 32)
                m = fmaxf(m, edge_scores[s0 + e]);
            #pragma unroll
            for (int off = 16; off > 0; off >>= 1)
                m = fmaxf(m, __shfl_xor_sync(FULL_MASK, m, off));

            float sum = 0.0f;
            for (int e = lane; e < deg; e += 32)
                sum += __expf(edge_scores[s0 + e] - m);
            #pragma unroll
            for (int off = 16; off > 0; off >>= 1)
                sum += __shfl_xor_sync(FULL_MASK, sum, off);
            const float inv = (deg > 0) ? __frcp_rn(sum) : 0.0f;

            float4 acc = make_float4(0.0f, 0.0f, 0.0f, 0.0f);
            for (int e = 0; e < deg; e++) {
                const float bs = edge_scores[s0 + e];
                const unsigned bc = (unsigned)load_index(col_idx_raw, s0 + e, is64);
                const float bw = __expf(bs - m) * inv;
                const float4 v = node_value4[(size_t)bc * 16 + sub];
                acc.x = fmaf(bw, v.x, acc.x);
                acc.y = fmaf(bw, v.y, acc.y);
                acc.z = fmaf(bw, v.z, acc.z);
                acc.w = fmaf(bw, v.w, acc.w);
            }
            if (half == 0)
                out4[(size_t)node * 16 + sub] = acc;
        }
    }
}

extern "C" void kernel_launch(void* const* d_in, const int* in_sizes, int n_in,
                              void* d_out, int out_size)
{
    const void*   row_ptr     = d_in[0];
    const void*   col_idx     = d_in[1];
    const float*  edge_scores = (const float*)d_in[2];
    const float4* node_value4 = (const float4*)d_in[3];
    float4*       out4        = (float4*)d_out;

    const int num_nodes = in_sizes[0] - 1;
    const int n_f4 = in_sizes[3] / 4;

    if (num_nodes <= MAX_NODES)
        convert_to_half_kernel<<<(n_f4 + 255) / 256, 256>>>(node_value4, n_f4);

    const int num_pairs = (num_nodes + 1) / 2;
    const int grid = (num_pairs + WARPS_PER_BLOCK - 1) / WARPS_PER_BLOCK;

    gat_aggregate_kernel<<<grid, THREADS_PER_BLOCK>>>(
        row_ptr, col_idx, edge_scores, node_value4, out4, num_nodes);
}

// round 8
// speedup vs baseline: 1.1216x; 1.1216x over previous
#include <cuda_runtime.h>
#include <cuda_fp16.h>
#include <math.h>

#define WARPS_PER_BLOCK 8
#define THREADS_PER_BLOCK (WARPS_PER_BLOCK * 32)
#define FULL_MASK 0xffffffffu
#define MAX_NODES 100000
#define FEAT 64

// fp16 staging of node_value: one row = 64 halves = 128B = ONE L2 line.
// Viewed as uint4: 8 uint4 per row; lane (lane&7) owns features [8*s, 8*s+8).
__device__ uint4 g_value_h[(size_t)MAX_NODES * (FEAT / 8)];

// Index width (int32 vs int64) detected from raw words of row_ptr:
//   int32: [0, D, 2D, ...]  -> raw[1] != 0
//   int64: [0,0, D,0, ...]  -> raw[1] == 0 && raw[2] != 0
__device__ __forceinline__ long long load_index(const void* p, long long i, int is64)
{
    return is64 ? ((const long long*)p)[i] : (long long)((const int*)p)[i];
}

// packed f32x2 fma: acc = v * w2 + acc   (Blackwell FFMA2)
__device__ __forceinline__ void fma2(unsigned long long& acc,
                                     unsigned long long v,
                                     unsigned long long w2)
{
    asm("fma.rn.f32x2 %0, %1, %2, %0;" : "+l"(acc) : "l"(v), "l"(w2));
}

__device__ __forceinline__ unsigned long long h2_to_f2(unsigned h2raw)
{
    const float2 f = __half22float2(*reinterpret_cast<const __half2*>(&h2raw));
    unsigned long long r;
    asm("mov.b64 %0, {%1, %2};" : "=l"(r) : "f"(f.x), "f"(f.y));
    return r;
}

__global__ void __launch_bounds__(256)
convert_to_half_kernel(const float4* __restrict__ node_value4, int n_f4)
{
    const int i = blockIdx.x * blockDim.x + threadIdx.x;
    if (i < n_f4) {
        const float4 f = node_value4[i];
        uint2 h;
        *reinterpret_cast<__half2*>(&h.x) = __floats2half2_rn(f.x, f.y);
        *reinterpret_cast<__half2*>(&h.y) = __floats2half2_rn(f.z, f.w);
        reinterpret_cast<uint2*>(g_value_h)[i] = h;
    }
}

// FOUR nodes per warp (their 64 CSR edges contiguous). Lane loads one
// float2 score-pair + col-pair (edges 2l, 2l+1). Softmax per 8-lane quarter
// (butterfly 4,2,1). Gather: quarter q serves node 4p+q; lane owns 8
// features (uint4 of fp16); one LDG.128 serves one edge of EACH node.
// Accumulation uses packed f32x2 FMA (FFMA2).
__global__ void __launch_bounds__(THREADS_PER_BLOCK)
gat_aggregate_kernel(const void*   __restrict__ row_ptr_raw,
                     const void*   __restrict__ col_idx_raw,
                     const float*  __restrict__ edge_scores,
                     const float4* __restrict__ node_value4,  // fp32 fallback
                     float4*       __restrict__ out4,         // [N, 16] float4
                     int num_nodes)
{
    const int quad  = blockIdx.x * WARPS_PER_BLOCK + (threadIdx.x >> 5);
    const int node0 = 4 * quad;
    if (node0 >= num_nodes) return;
    const int lane = threadIdx.x & 31;

    // uniform per-grid: detect index width (L2-broadcast loads, ~free)
    const unsigned* rp_raw = (const unsigned*)row_ptr_raw;
    const int is64 = (rp_raw[1] == 0u && rp_raw[2] != 0u) ? 1 : 0;

    bool fast = (node0 + 4 <= num_nodes) && (num_nodes <= MAX_NODES);
    long long r0 = 0;
    if (fast) {
        r0 = load_index(row_ptr_raw, node0, is64);
        const long long r1 = load_index(row_ptr_raw, node0 + 1, is64);
        const long long r2 = load_index(row_ptr_raw, node0 + 2, is64);
        const long long r3 = load_index(row_ptr_raw, node0 + 3, is64);
        const long long r4 = load_index(row_ptr_raw, node0 + 4, is64);
        fast = (r1 - r0 == 16) && (r2 - r1 == 16) && (r3 - r2 == 16) && (r4 - r3 == 16);
    }

    if (fast) {
        // ---- fast path: 4 nodes, all degree 16, fp16-staged gather ----
        // lane holds edges 2*lane and 2*lane+1 (node = lane>>3)
        const float2 s2 = *((const float2*)(edge_scores + r0) + lane);
        unsigned c0, c1;
        if (is64) {
            c0 = (unsigned)((const long long*)col_idx_raw)[r0 + 2 * lane];
            c1 = (unsigned)((const long long*)col_idx_raw)[r0 + 2 * lane + 1];
        } else {
            const int2 cc = *((const int2*)((const int*)col_idx_raw + r0) + lane);
            c0 = (unsigned)cc.x; c1 = (unsigned)cc.y;
        }

        // per-quarter softmax (8 lanes = 16 edges = one node)
        float m = fmaxf(s2.x, s2.y);
        #pragma unroll
        for (int off = 4; off > 0; off >>= 1)
            m = fmaxf(m, __shfl_xor_sync(FULL_MASK, m, off));

        float w0 = __expf(s2.x - m);
        float w1 = __expf(s2.y - m);
        float sum = w0 + w1;
        #pragma unroll
        for (int off = 4; off > 0; off >>= 1)
            sum += __shfl_xor_sync(FULL_MASK, sum, off);
        const float inv = __frcp_rn(sum);
        w0 *= inv; w1 *= inv;

        const int qbase = lane & 0x18;          // quarter base lane
        const int sub8  = lane & 7;             // uint4 slot within the row
        const char* vbase = (const char*)g_value_h + (sub8 << 4);

        unsigned long long a0 = 0, a1 = 0, a2 = 0, a3 = 0;  // 8 f32 accs

        #pragma unroll
        for (int e = 0; e < 16; e++) {
            const int src = qbase + (e >> 1);
            const float    bw = __shfl_sync(FULL_MASK, (e & 1) ? w1 : w0, src);
            const unsigned bc = __shfl_sync(FULL_MASK, (e & 1) ? c1 : c0, src);

            const uint4 hv = *(const uint4*)(vbase + ((size_t)bc << 7));

            unsigned long long w2;
            asm("mov.b64 %0, {%1, %1};" : "=l"(w2) : "f"(bw));

            fma2(a0, h2_to_f2(hv.x), w2);
            fma2(a1, h2_to_f2(hv.y), w2);
            fma2(a2, h2_to_f2(hv.z), w2);
            fma2(a3, h2_to_f2(hv.w), w2);
        }

        float f0, f1, f2, f3, f4, f5, f6, f7;
        asm("mov.b64 {%0, %1}, %2;" : "=f"(f0), "=f"(f1) : "l"(a0));
        asm("mov.b64 {%0, %1}, %2;" : "=f"(f2), "=f"(f3) : "l"(a1));
        asm("mov.b64 {%0, %1}, %2;" : "=f"(f4), "=f"(f5) : "l"(a2));
        asm("mov.b64 {%0, %1}, %2;" : "=f"(f6), "=f"(f7) : "l"(a3));

        const int node = node0 + (lane >> 3);
        const size_t ob = (size_t)node * 16 + sub8 * 2;
        out4[ob]     = make_float4(f0, f1, f2, f3);
        out4[ob + 1] = make_float4(f4, f5, f6, f7);
    } else {
        // ---- generic path: any degree, full fp32 (not taken here) ----
        const int half = lane >> 4;
        const int sub  = lane & 15;
        for (int which = 0; which < 4; which++) {
            const int node = node0 + which;
            if (node >= num_nodes) break;
            const long long s0 = load_index(row_ptr_raw, node, is64);
            const long long s1 = load_index(row_ptr_raw, node + 1, is64);
            const int deg = (int)(s1 - s0);

            float m = -INFINITY;
            for (int e = lane; e < deg; e += 32)
                m = fmaxf(m, edge_scores[s0 + e]);
            #pragma unroll
            for (int off = 16; off > 0; off >>= 1)
                m = fmaxf(m, __shfl_xor_sync(FULL_MASK, m, off));

            float sum = 0.0f;
            for (int e = lane; e < deg; e += 32)
                sum += __expf(edge_scores[s0 + e] - m);
            #pragma unroll
            for (int off = 16; off > 0; off >>= 1)
                sum += __shfl_xor_sync(FULL_MASK, sum, off);
            const float inv = (deg > 0) ? __frcp_rn(sum) : 0.0f;

            float4 acc = make_float4(0.0f, 0.0f, 0.0f, 0.0f);
            for (int e = 0; e < deg; e++) {
                const float bs = edge_scores[s0 + e];
                const unsigned bc = (unsigned)load_index(col_idx_raw, s0 + e, is64);
                const float bw = __expf(bs - m) * inv;
                const float4 v = node_value4[(size_t)bc * 16 + sub];
                acc.x = fmaf(bw, v.x, acc.x);
                acc.y = fmaf(bw, v.y, acc.y);
                acc.z = fmaf(bw, v.z, acc.z);
                acc.w = fmaf(bw, v.w, acc.w);
            }
            if (half == 0)
                out4[(size_t)node * 16 + sub] = acc;
        }
    }
}

extern "C" void kernel_launch(void* const* d_in, const int* in_sizes, int n_in,
                              void* d_out, int out_size)
{
    const void*   row_ptr     = d_in[0];
    const void*   col_idx     = d_in[1];
    const float*  edge_scores = (const float*)d_in[2];
    const float4* node_value4 = (const float4*)d_in[3];
    float4*       out4        = (float4*)d_out;

    const int num_nodes = in_sizes[0] - 1;
    const int n_f4 = in_sizes[3] / 4;

    if (num_nodes <= MAX_NODES)
        convert_to_half_kernel<<<(n_f4 + 255) / 256, 256>>>(node_value4, n_f4);

    const int num_quads = (num_nodes + 3) / 4;
    const int grid = (num_quads + WARPS_PER_BLOCK - 1) / WARPS_PER_BLOCK;

    gat_aggregate_kernel<<<grid, THREADS_PER_BLOCK>>>(
        row_ptr, col_idx, edge_scores, node_value4, out4, num_nodes);
}

// round 9
// speedup vs baseline: 1.2089x; 1.0778x over previous
#include <cuda_runtime.h>
#include <cuda_fp16.h>
#include <math.h>

#define WARPS_PER_BLOCK 8
#define THREADS_PER_BLOCK (WARPS_PER_BLOCK * 32)
#define FULL_MASK 0xffffffffu
#define MAX_NODES 100000
#define FEAT 64

// fp16 staging of node_value: one row = 64 halves = 128B = ONE L2 line.
// Viewed as uint4: 8 uint4 per row; lane (lane&7) owns features [8*s, 8*s+8).
__device__ uint4 g_value_h[(size_t)MAX_NODES * (FEAT / 8)];

// Index width (int32 vs int64) detected from raw words of row_ptr:
//   int32: [0, D, 2D, ...]  -> raw[1] != 0
//   int64: [0,0, D,0, ...]  -> raw[1] == 0 && raw[2] != 0
__device__ __forceinline__ long long load_index(const void* p, long long i, int is64)
{
    return is64 ? ((const long long*)p)[i] : (long long)((const int*)p)[i];
}

// packed f32x2 fma: acc = v * w2 + acc   (Blackwell FFMA2)
__device__ __forceinline__ void fma2(unsigned long long& acc,
                                     unsigned long long v,
                                     unsigned long long w2)
{
    asm("fma.rn.f32x2 %0, %1, %2, %0;" : "+l"(acc) : "l"(v), "l"(w2));
}

__device__ __forceinline__ unsigned long long h2_to_f2(unsigned h2raw)
{
    const float2 f = __half22float2(*reinterpret_cast<const __half2*>(&h2raw));
    unsigned long long r;
    asm("mov.b64 %0, {%1, %2};" : "=l"(r) : "f"(f.x), "f"(f.y));
    return r;
}

__global__ void __launch_bounds__(512)
convert_to_half_kernel(const float4* __restrict__ node_value4, int n_u4)
{
    const int i = blockIdx.x * blockDim.x + threadIdx.x;
    if (i < n_u4) {
        const float4 fa = node_value4[2 * i];
        const float4 fb = node_value4[2 * i + 1];
        uint4 h;
        *reinterpret_cast<__half2*>(&h.x) = __floats2half2_rn(fa.x, fa.y);
        *reinterpret_cast<__half2*>(&h.y) = __floats2half2_rn(fa.z, fa.w);
        *reinterpret_cast<__half2*>(&h.z) = __floats2half2_rn(fb.x, fb.y);
        *reinterpret_cast<__half2*>(&h.w) = __floats2half2_rn(fb.z, fb.w);
        g_value_h[i] = h;
    }
}

// FOUR nodes per warp (their 64 CSR edges contiguous). Lane loads one
// float2 score-pair + col-pair (edges 2l, 2l+1). Softmax per 8-lane quarter
// (butterfly 4,2,1). Gather: quarter q serves node 4p+q; lane owns 8
// features (uint4 of fp16). Each iteration handles an edge PAIR: both
// LDG.128s issued back-to-back (guaranteed MLP>=2), then consumed with
// packed f32x2 FMA. __launch_bounds__(.,7) keeps regs<=36 -> 56 warps/SM.
__global__ void __launch_bounds__(THREADS_PER_BLOCK, 7)
gat_aggregate_kernel(const void*   __restrict__ row_ptr_raw,
                     const void*   __restrict__ col_idx_raw,
                     const float*  __restrict__ edge_scores,
                     const float4* __restrict__ node_value4,  // fp32 fallback
                     float4*       __restrict__ out4,         // [N, 16] float4
                     int num_nodes)
{
    const int quad  = blockIdx.x * WARPS_PER_BLOCK + (threadIdx.x >> 5);
    const int node0 = 4 * quad;
    if (node0 >= num_nodes) return;
    const int lane = threadIdx.x & 31;

    // uniform per-grid: detect index width (L2-broadcast loads, ~free)
    const unsigned* rp_raw = (const unsigned*)row_ptr_raw;
    const int is64 = (rp_raw[1] == 0u && rp_raw[2] != 0u) ? 1 : 0;

    bool fast = (node0 + 4 <= num_nodes) && (num_nodes <= MAX_NODES);
    long long r0 = 0;
    if (fast) {
        r0 = load_index(row_ptr_raw, node0, is64);
        const long long r4 = load_index(row_ptr_raw, node0 + 4, is64);
        const long long r1 = load_index(row_ptr_raw, node0 + 1, is64);
        const long long r2 = load_index(row_ptr_raw, node0 + 2, is64);
        const long long r3 = load_index(row_ptr_raw, node0 + 3, is64);
        fast = (r1 - r0 == 16) && (r2 - r1 == 16) && (r3 - r2 == 16) && (r4 - r3 == 16);
    }

    if (fast) {
        // ---- fast path: 4 nodes, all degree 16, fp16-staged gather ----
        const float2 s2 = *((const float2*)(edge_scores + r0) + lane);
        unsigned c0, c1;
        if (is64) {
            c0 = (unsigned)((const long long*)col_idx_raw)[r0 + 2 * lane];
            c1 = (unsigned)((const long long*)col_idx_raw)[r0 + 2 * lane + 1];
        } else {
            const int2 cc = *((const int2*)((const int*)col_idx_raw + r0) + lane);
            c0 = (unsigned)cc.x; c1 = (unsigned)cc.y;
        }

        // per-quarter softmax (8 lanes = 16 edges = one node)
        float m = fmaxf(s2.x, s2.y);
        #pragma unroll
        for (int off = 4; off > 0; off >>= 1)
            m = fmaxf(m, __shfl_xor_sync(FULL_MASK, m, off));

        float w0 = __expf(s2.x - m);
        float w1 = __expf(s2.y - m);
        float sum = w0 + w1;
        #pragma unroll
        for (int off = 4; off > 0; off >>= 1)
            sum += __shfl_xor_sync(FULL_MASK, sum, off);
        const float inv = __frcp_rn(sum);
        w0 *= inv; w1 *= inv;

        const int qbase = lane & 0x18;          // quarter base lane
        const int sub8  = lane & 7;             // uint4 slot within the row
        const char* vbase = (const char*)g_value_h + (sub8 << 4);

        unsigned long long a0 = 0, a1 = 0, a2 = 0, a3 = 0;  // 8 f32 accs

        #pragma unroll
        for (int e8 = 0; e8 < 8; e8++) {
            const int src = qbase + e8;
            const float    bwA = __shfl_sync(FULL_MASK, w0, src);
            const unsigned bcA = __shfl_sync(FULL_MASK, c0, src);
            const float    bwB = __shfl_sync(FULL_MASK, w1, src);
            const unsigned bcB = __shfl_sync(FULL_MASK, c1, src);

            // both loads issued before either is consumed (MLP >= 2)
            const uint4 hA = *(const uint4*)(vbase + ((size_t)bcA << 7));
            const uint4 hB = *(const uint4*)(vbase + ((size_t)bcB << 7));

            unsigned long long w2A, w2B;
            asm("mov.b64 %0, {%1, %1};" : "=l"(w2A) : "f"(bwA));
            asm("mov.b64 %0, {%1, %1};" : "=l"(w2B) : "f"(bwB));

            fma2(a0, h2_to_f2(hA.x), w2A);
            fma2(a1, h2_to_f2(hA.y), w2A);
            fma2(a2, h2_to_f2(hA.z), w2A);
            fma2(a3, h2_to_f2(hA.w), w2A);

            fma2(a0, h2_to_f2(hB.x), w2B);
            fma2(a1, h2_to_f2(hB.y), w2B);
            fma2(a2, h2_to_f2(hB.z), w2B);
            fma2(a3, h2_to_f2(hB.w), w2B);
        }

        float f0, f1, f2, f3, f4, f5, f6, f7;
        asm("mov.b64 {%0, %1}, %2;" : "=f"(f0), "=f"(f1) : "l"(a0));
        asm("mov.b64 {%0, %1}, %2;" : "=f"(f2), "=f"(f3) : "l"(a1));
        asm("mov.b64 {%0, %1}, %2;" : "=f"(f4), "=f"(f5) : "l"(a2));
        asm("mov.b64 {%0, %1}, %2;" : "=f"(f6), "=f"(f7) : "l"(a3));

        const int node = node0 + (lane >> 3);
        const size_t ob = (size_t)node * 16 + sub8 * 2;
        out4[ob]     = make_float4(f0, f1, f2, f3);
        out4[ob + 1] = make_float4(f4, f5, f6, f7);
    } else {
        // ---- generic path: any degree, full fp32 (not taken here) ----
        const int half = lane >> 4;
        const int sub  = lane & 15;
        for (int which = 0; which < 4; which++) {
            const int node = node0 + which;
            if (node >= num_nodes) break;
            const long long s0 = load_index(row_ptr_raw, node, is64);
            const long long s1 = load_index(row_ptr_raw, node + 1, is64);
            const int deg = (int)(s1 - s0);

            float m = -INFINITY;
            for (int e = lane; e < deg; e += 32)
                m = fmaxf(m, edge_scores[s0 + e]);
            #pragma unroll
            for (int off = 16; off > 0; off >>= 1)
                m = fmaxf(m, __shfl_xor_sync(FULL_MASK, m, off));

            float sum = 0.0f;
            for (int e = lane; e < deg; e += 32)
                sum += __expf(edge_scores[s0 + e] - m);
            #pragma unroll
            for (int off = 16; off > 0; off >>= 1)
                sum += __shfl_xor_sync(FULL_MASK, sum, off);
            const float inv = (deg > 0) ? __frcp_rn(sum) : 0.0f;

            float4 acc = make_float4(0.0f, 0.0f, 0.0f, 0.0f);
            for (int e = 0; e < deg; e++) {
                const float bs = edge_scores[s0 + e];
                const unsigned bc = (unsigned)load_index(col_idx_raw, s0 + e, is64);
                const float bw = __expf(bs - m) * inv;
                const float4 v = node_value4[(size_t)bc * 16 + sub];
                acc.x = fmaf(bw, v.x, acc.x);
                acc.y = fmaf(bw, v.y, acc.y);
                acc.z = fmaf(bw, v.z, acc.z);
                acc.w = fmaf(bw, v.w, acc.w);
            }
            if (half == 0)
                out4[(size_t)node * 16 + sub] = acc;
        }
    }
}

extern "C" void kernel_launch(void* const* d_in, const int* in_sizes, int n_in,
                              void* d_out, int out_size)
{
    const void*   row_ptr     = d_in[0];
    const void*   col_idx     = d_in[1];
    const float*  edge_scores = (const float*)d_in[2];
    const float4* node_value4 = (const float4*)d_in[3];
    float4*       out4        = (float4*)d_out;

    const int num_nodes = in_sizes[0] - 1;
    const int n_u4 = in_sizes[3] / 8;

    if (num_nodes <= MAX_NODES)
        convert_to_half_kernel<<<(n_u4 + 511) / 512, 512>>>(node_value4, n_u4);

    const int num_quads = (num_nodes + 3) / 4;
    const int grid = (num_quads + WARPS_PER_BLOCK - 1) / WARPS_PER_BLOCK;

    gat_aggregate_kernel<<<grid, THREADS_PER_BLOCK>>>(
        row_ptr, col_idx, edge_scores, node_value4, out4, num_nodes);
}